// round 13
// baseline (speedup 1.0000x reference)
#include <cuda_runtime.h>
#include <cuda_fp16.h>
#include <math.h>

#define NMAX 50000
#define EMAX 800000
#define DMAX 128

// Scratch (device globals; no allocation in kernel_launch)
__device__ __half g_hs[NMAX * DMAX];   // h (= x@W) payload in fp16
__device__ float g_x[NMAX * DMAX];     // layer activations (fp32)
__device__ float g_dis[NMAX];          // rsqrt(deg+1)
__device__ float g_s[NMAX];            // node scores
__device__ int   g_counts[NMAX];       // in-degree histogram
__device__ int   g_offsets[NMAX + 1];  // CSR row offsets
__device__ int   g_cursor[NMAX];       // fill cursors
__device__ int   g_csr[EMAX];          // CSR src indices grouped by dst
__device__ int   g_bsums[256];         // scan block partials

// ---------------------------------------------------------------------------
// f32x2 packed-FMA helpers (sm_103a dual fp32 path)
__device__ __forceinline__ unsigned long long pack2(float x) {
    unsigned long long r;
    asm("mov.b64 %0, {%1, %1};" : "=l"(r) : "f"(x));
    return r;
}
__device__ __forceinline__ void fma2(unsigned long long& d,
                                     unsigned long long a,
                                     unsigned long long b) {
    asm("fma.rn.f32x2 %0, %1, %2, %3;" : "=l"(d) : "l"(a), "l"(b), "l"(d));
}
__device__ __forceinline__ float2 unpack2(unsigned long long v) {
    float2 f;
    asm("mov.b64 {%0, %1}, %2;" : "=f"(f.x), "=f"(f.y) : "l"(v));
    return f;
}

// ---------------------------------------------------------------------------
// Histogram, 4 edges per thread (int4)
__global__ void hist_kernel(const int* __restrict__ dst, int E, int* counts) {
    int i = blockIdx.x * blockDim.x + threadIdx.x;
    int E4 = E >> 2;
    if (i < E4) {
        int4 d = ((const int4*)dst)[i];
        atomicAdd(&counts[d.x], 1);
        atomicAdd(&counts[d.y], 1);
        atomicAdd(&counts[d.z], 1);
        atomicAdd(&counts[d.w], 1);
    }
    int t = E4 * 4 + i;
    if (i < (E & 3)) atomicAdd(&counts[dst[t]], 1);
}

// Two-level exclusive scan
__global__ void blocksum_kernel(const int* __restrict__ counts, int* bsums, int n) {
    __shared__ int sh[256];
    int i = blockIdx.x * 256 + threadIdx.x;
    sh[threadIdx.x] = (i < n) ? counts[i] : 0;
    __syncthreads();
#pragma unroll
    for (int off = 128; off > 0; off >>= 1) {
        if (threadIdx.x < off) sh[threadIdx.x] += sh[threadIdx.x + off];
        __syncthreads();
    }
    if (threadIdx.x == 0) bsums[blockIdx.x] = sh[0];
}

__global__ void scan_bsums_kernel(int* bsums, int nb, int* offsets, int n) {
    __shared__ int sh[256];
    int t = threadIdx.x;
    int v = (t < nb) ? bsums[t] : 0;
    sh[t] = v;
    __syncthreads();
#pragma unroll
    for (int off = 1; off < 256; off <<= 1) {
        int u = (t >= off) ? sh[t - off] : 0;
        __syncthreads();
        sh[t] += u;
        __syncthreads();
    }
    if (t < nb) bsums[t] = sh[t] - v;  // exclusive
    if (t == 255) offsets[n] = sh[255];
}

__global__ void offsets_kernel(const int* __restrict__ counts,
                               const int* __restrict__ bsums,
                               int* offsets, int* cursor, float* dis, int n) {
    __shared__ int sh[256];
    int t = threadIdx.x;
    int i = blockIdx.x * 256 + t;
    int v = (i < n) ? counts[i] : 0;
    sh[t] = v;
    __syncthreads();
#pragma unroll
    for (int off = 1; off < 256; off <<= 1) {
        int u = (t >= off) ? sh[t - off] : 0;
        __syncthreads();
        sh[t] += u;
        __syncthreads();
    }
    if (i < n) {
        int o = bsums[blockIdx.x] + sh[t] - v;
        offsets[i] = o;
        cursor[i] = o;
        dis[i] = rsqrtf((float)v + 1.0f);
    }
}

// CSR fill, 4 edges per thread
__global__ void fill_kernel(const int* __restrict__ src,
                            const int* __restrict__ dst, int E,
                            int* cursor, int* __restrict__ csr) {
    int i = blockIdx.x * blockDim.x + threadIdx.x;
    int E4 = E >> 2;
    if (i < E4) {
        int4 s = ((const int4*)src)[i];
        int4 d = ((const int4*)dst)[i];
        int p0 = atomicAdd(&cursor[d.x], 1);
        int p1 = atomicAdd(&cursor[d.y], 1);
        int p2 = atomicAdd(&cursor[d.z], 1);
        int p3 = atomicAdd(&cursor[d.w], 1);
        csr[p0] = s.x;
        csr[p1] = s.y;
        csr[p2] = s.z;
        csr[p3] = s.w;
    }
    int t = E4 * 4 + i;
    if (i < (E & 3)) {
        int pos = atomicAdd(&cursor[dst[t]], 1);
        csr[pos] = src[t];
    }
}

// ---------------------------------------------------------------------------
// Register-blocked SGEMM (f32x2 FMAs), fp32 accumulate, fp16 output.
// out[r, c] = half((A@W)[r, c] * (SCALE ? dis[r] : 1)).  BM=128, 256 threads.
template <int DIN, int DOUT, bool SCALE>
__global__ void gemm_scale_kernel(const float* __restrict__ A,
                                  const float* __restrict__ W,
                                  const float* __restrict__ dis,
                                  __half* __restrict__ out, int n) {
    constexpr int BM = 128, BK = 8, TN = 8;
    constexpr int TX = DOUT / TN;
    constexpr int TY = 256 / TX;
    constexpr int TM = BM / TY;

    __shared__ float As[BK][BM + 4];
    __shared__ float Ws[BK][DOUT];

    int tid = threadIdx.x;
    int tx = tid % TX, ty = tid / TX;
    int row0 = blockIdx.x * BM;

    unsigned long long acc[TM][TN / 2] = {};

    for (int k0 = 0; k0 < DIN; k0 += BK) {
        {
            int r = tid >> 1;
            int kk = (tid & 1) * 4;
            int grow = row0 + r;
            float4 v = make_float4(0.f, 0.f, 0.f, 0.f);
            if (grow < n) v = *(const float4*)&A[grow * DIN + k0 + kk];
            As[kk][r] = v.x;
            As[kk + 1][r] = v.y;
            As[kk + 2][r] = v.z;
            As[kk + 3][r] = v.w;
        }
        {
            const float4* wsrc = (const float4*)(W + k0 * DOUT);
            float4* wdst = (float4*)&Ws[0][0];
#pragma unroll
            for (int i = tid; i < BK * DOUT / 4; i += 256) wdst[i] = wsrc[i];
        }
        __syncthreads();

#pragma unroll
        for (int k = 0; k < BK; k++) {
            unsigned long long b2[TN / 2];
            const unsigned long long* wp =
                (const unsigned long long*)&Ws[k][tx * TN];
#pragma unroll
            for (int j = 0; j < TN / 2; j++) b2[j] = wp[j];
#pragma unroll
            for (int i = 0; i < TM; i++) {
                unsigned long long rp = pack2(As[k][ty * TM + i]);
#pragma unroll
                for (int j = 0; j < TN / 2; j++) fma2(acc[i][j], rp, b2[j]);
            }
        }
        __syncthreads();
    }

#pragma unroll
    for (int i = 0; i < TM; i++) {
        int r = row0 + ty * TM + i;
        if (r < n) {
            float dv = SCALE ? dis[r] : 1.0f;
            float2 p0 = unpack2(acc[i][0]);
            float2 p1 = unpack2(acc[i][1]);
            float2 p2 = unpack2(acc[i][2]);
            float2 p3 = unpack2(acc[i][3]);
            __half2 q0 = __float22half2_rn(make_float2(p0.x * dv, p0.y * dv));
            __half2 q1 = __float22half2_rn(make_float2(p1.x * dv, p1.y * dv));
            __half2 q2 = __float22half2_rn(make_float2(p2.x * dv, p2.y * dv));
            __half2 q3 = __float22half2_rn(make_float2(p3.x * dv, p3.y * dv));
            uint4 pk = make_uint4(*(unsigned*)&q0, *(unsigned*)&q1,
                                  *(unsigned*)&q2, *(unsigned*)&q3);
            *(uint4*)&out[r * DOUT + tx * TN] = pk;
        }
    }
}

// ---------------------------------------------------------------------------
// fp16 vector loads, fp32 accumulate.
template <int VW>
__device__ __forceinline__ void vload_add_h(const __half* __restrict__ p, float* a) {
    if constexpr (VW == 4) {
        uint2 u = *(const uint2*)p;
        float2 f0 = __half22float2(*(const __half2*)&u.x);
        float2 f1 = __half22float2(*(const __half2*)&u.y);
        a[0] += f0.x; a[1] += f0.y; a[2] += f1.x; a[3] += f1.y;
    } else if constexpr (VW == 2) {
        __half2 h = *(const __half2*)p;
        float2 f = __half22float2(h);
        a[0] += f.x; a[1] += f.y;
    } else {
        a[0] += __half2float(*p);
    }
}
template <int VW>
__device__ __forceinline__ void vload_fma_h(const __half* __restrict__ p, float s,
                                            float* a) {
    if constexpr (VW == 4) {
        uint2 u = *(const uint2*)p;
        float2 f0 = __half22float2(*(const __half2*)&u.x);
        float2 f1 = __half22float2(*(const __half2*)&u.y);
        a[0] += f0.x * s; a[1] += f0.y * s; a[2] += f1.x * s; a[3] += f1.y * s;
    } else if constexpr (VW == 2) {
        __half2 h = *(const __half2*)p;
        float2 f = __half22float2(h);
        a[0] += f.x * s; a[1] += f.y * s;
    } else {
        a[0] += __half2float(*p) * s;
    }
}

// One warp per node, edge loop unrolled x8, 4 independent accumulators.
// EDGE_SCALE=false: hs = h*dis[row] (fp16); out = relu(dis[v]*(acc+hs[v]) + b)
// EDGE_SCALE=true:  hs = h (fp16); acc = sum h[src]*dis[src];
//   out = relu(dis[v]*(acc + h[v]*dis[v]) + b)
template <int DOUT, bool EDGE_SCALE>
__global__ void __launch_bounds__(256)
gather_combine_kernel(const __half* __restrict__ hs,
                      const int* __restrict__ csr,
                      const int* __restrict__ offsets,
                      const float* __restrict__ b,
                      const float* __restrict__ dis,
                      float* __restrict__ out, int n) {
    constexpr int VW = DOUT / 32;
    int warp = (blockIdx.x * blockDim.x + threadIdx.x) >> 5;
    int lane = threadIdx.x & 31;
    if (warp >= n) return;
    int v = warp;
    int s0 = offsets[v], s1 = offsets[v + 1];

    float a0[VW] = {}, a1[VW] = {}, a2[VW] = {}, a3[VW] = {};
    int fo = lane * VW;
    const __half* __restrict__ base = hs + fo;

    int e = s0;
    for (; e + 8 <= s1; e += 8) {
        int i0 = __ldg(&csr[e]);
        int i1 = __ldg(&csr[e + 1]);
        int i2 = __ldg(&csr[e + 2]);
        int i3 = __ldg(&csr[e + 3]);
        int i4 = __ldg(&csr[e + 4]);
        int i5 = __ldg(&csr[e + 5]);
        int i6 = __ldg(&csr[e + 6]);
        int i7 = __ldg(&csr[e + 7]);
        if constexpr (EDGE_SCALE) {
            float d0 = __ldg(&dis[i0]);
            float d1 = __ldg(&dis[i1]);
            float d2 = __ldg(&dis[i2]);
            float d3 = __ldg(&dis[i3]);
            float d4 = __ldg(&dis[i4]);
            float d5 = __ldg(&dis[i5]);
            float d6 = __ldg(&dis[i6]);
            float d7 = __ldg(&dis[i7]);
            vload_fma_h<VW>(base + (size_t)i0 * DOUT, d0, a0);
            vload_fma_h<VW>(base + (size_t)i1 * DOUT, d1, a1);
            vload_fma_h<VW>(base + (size_t)i2 * DOUT, d2, a2);
            vload_fma_h<VW>(base + (size_t)i3 * DOUT, d3, a3);
            vload_fma_h<VW>(base + (size_t)i4 * DOUT, d4, a0);
            vload_fma_h<VW>(base + (size_t)i5 * DOUT, d5, a1);
            vload_fma_h<VW>(base + (size_t)i6 * DOUT, d6, a2);
            vload_fma_h<VW>(base + (size_t)i7 * DOUT, d7, a3);
        } else {
            vload_add_h<VW>(base + (size_t)i0 * DOUT, a0);
            vload_add_h<VW>(base + (size_t)i1 * DOUT, a1);
            vload_add_h<VW>(base + (size_t)i2 * DOUT, a2);
            vload_add_h<VW>(base + (size_t)i3 * DOUT, a3);
            vload_add_h<VW>(base + (size_t)i4 * DOUT, a0);
            vload_add_h<VW>(base + (size_t)i5 * DOUT, a1);
            vload_add_h<VW>(base + (size_t)i6 * DOUT, a2);
            vload_add_h<VW>(base + (size_t)i7 * DOUT, a3);
        }
    }
    for (; e + 2 <= s1; e += 2) {
        int i0 = __ldg(&csr[e]);
        int i1 = __ldg(&csr[e + 1]);
        if constexpr (EDGE_SCALE) {
            float d0 = __ldg(&dis[i0]);
            float d1 = __ldg(&dis[i1]);
            vload_fma_h<VW>(base + (size_t)i0 * DOUT, d0, a0);
            vload_fma_h<VW>(base + (size_t)i1 * DOUT, d1, a1);
        } else {
            vload_add_h<VW>(base + (size_t)i0 * DOUT, a0);
            vload_add_h<VW>(base + (size_t)i1 * DOUT, a1);
        }
    }
    if (e < s1) {
        int i0 = __ldg(&csr[e]);
        if constexpr (EDGE_SCALE) {
            float d0 = __ldg(&dis[i0]);
            vload_fma_h<VW>(base + (size_t)i0 * DOUT, d0, a2);
        } else {
            vload_add_h<VW>(base + (size_t)i0 * DOUT, a2);
        }
    }

    float dv = dis[v];
    const __half* hp = hs + (size_t)v * DOUT + fo;
    float* op = out + (size_t)v * DOUT + fo;

    // Self term: hs[v] (already row-scaled when !EDGE_SCALE) or h[v]*dis[v].
    float self[VW] = {};
    if constexpr (EDGE_SCALE) {
        vload_fma_h<VW>(hp, dv, self);
    } else {
        vload_add_h<VW>(hp, self);
    }

#pragma unroll
    for (int j = 0; j < VW; j++) {
        float r = dv * ((a0[j] + a1[j]) + (a2[j] + a3[j]) + self[j]) + b[fo + j];
        op[j] = r > 0.0f ? r : 0.0f;
    }
}

// ---------------------------------------------------------------------------
__global__ void mlp_kernel(const float* __restrict__ x,
                           const float* __restrict__ lw0, const float* __restrict__ lb0,
                           const float* __restrict__ lw1, const float* __restrict__ lb1,
                           const float* __restrict__ lw2, const float* __restrict__ lb2,
                           float* __restrict__ s, int n) {
    __shared__ float w0[32 * 16], b0[16], w1[16 * 8], b1[8], w2[8], b2s[1];
    int t = threadIdx.x;
    for (int j = t; j < 32 * 16; j += blockDim.x) w0[j] = lw0[j];
    for (int j = t; j < 16; j += blockDim.x) b0[j] = lb0[j];
    for (int j = t; j < 16 * 8; j += blockDim.x) w1[j] = lw1[j];
    for (int j = t; j < 8; j += blockDim.x) b1[j] = lb1[j];
    for (int j = t; j < 8; j += blockDim.x) w2[j] = lw2[j];
    if (t == 0) b2s[0] = lb2[0];
    __syncthreads();

    int i = blockIdx.x * blockDim.x + t;
    if (i >= n) return;

    float xv[32];
#pragma unroll
    for (int k = 0; k < 32; k++) xv[k] = x[i * 32 + k];

    float y1[16];
#pragma unroll
    for (int j = 0; j < 16; j++) {
        float a = b0[j];
#pragma unroll
        for (int k = 0; k < 32; k++) a += xv[k] * w0[k * 16 + j];
        y1[j] = a > 0.0f ? a : 0.0f;
    }
    float y2[8];
#pragma unroll
    for (int j = 0; j < 8; j++) {
        float a = b1[j];
#pragma unroll
        for (int k = 0; k < 16; k++) a += y1[k] * w1[k * 8 + j];
        y2[j] = a > 0.0f ? a : 0.0f;
    }
    float z = b2s[0];
#pragma unroll
    for (int k = 0; k < 8; k++) z += y2[k] * w2[k];
    s[i] = 1.0f / (1.0f + expf(-z));
}

__global__ void edge_score_kernel(const int* __restrict__ pe,
                                  const float* __restrict__ s,
                                  float* __restrict__ out, int ep) {
    int i = blockIdx.x * blockDim.x + threadIdx.x;
    if (i < ep) {
        int2 p = ((const int2*)pe)[i];
        out[i] = s[p.x] * s[p.y];
    }
}

// ---------------------------------------------------------------------------
extern "C" void kernel_launch(void* const* d_in, const int* in_sizes, int n_in,
                              void* d_out, int out_size) {
    const float* x   = (const float*)d_in[0];
    const int* ei    = (const int*)d_in[1];
    const int* pe    = (const int*)d_in[2];
    const float* cw0 = (const float*)d_in[3];
    const float* cb0 = (const float*)d_in[4];
    const float* cw1 = (const float*)d_in[5];
    const float* cb1 = (const float*)d_in[6];
    const float* cw2 = (const float*)d_in[7];
    const float* cb2 = (const float*)d_in[8];
    const float* lw0 = (const float*)d_in[9];
    const float* lb0 = (const float*)d_in[10];
    const float* lw1 = (const float*)d_in[11];
    const float* lb1 = (const float*)d_in[12];
    const float* lw2 = (const float*)d_in[13];
    const float* lb2 = (const float*)d_in[14];
    float* out = (float*)d_out;

    const int N  = in_sizes[0] / 128;
    const int E  = in_sizes[1] / 2;
    const int EP = out_size;

    const int* src = ei;
    const int* dst = ei + E;

    float *xb, *dis, *sc;
    __half* hs;
    int *counts, *offsets, *cursor, *csr, *bsums;
    cudaGetSymbolAddress((void**)&hs, g_hs);
    cudaGetSymbolAddress((void**)&xb, g_x);
    cudaGetSymbolAddress((void**)&dis, g_dis);
    cudaGetSymbolAddress((void**)&sc, g_s);
    cudaGetSymbolAddress((void**)&counts, g_counts);
    cudaGetSymbolAddress((void**)&offsets, g_offsets);
    cudaGetSymbolAddress((void**)&cursor, g_cursor);
    cudaGetSymbolAddress((void**)&csr, g_csr);
    cudaGetSymbolAddress((void**)&bsums, g_bsums);

    // Lazy side-stream + events for capture-legal fork/join.
    static cudaStream_t s_side = nullptr;
    static cudaEvent_t ev_fork = nullptr, ev_join = nullptr;
    if (!s_side) {
        cudaStreamCreateWithFlags(&s_side, cudaStreamNonBlocking);
        cudaEventCreateWithFlags(&ev_fork, cudaEventDisableTiming);
        cudaEventCreateWithFlags(&ev_join, cudaEventDisableTiming);
    }

    const int B = 256;
    const int NB = (N + 255) / 256;
    const int E4 = (E + 3) / 4;
    int gwarp = (N * 32 + B - 1) / B;  // 1 warp per node

    // ---- fork: CSR build + dis on side stream, GEMM0 (unscaled) on main ----
    cudaEventRecord(ev_fork, 0);
    cudaStreamWaitEvent(s_side, ev_fork, 0);

    cudaMemsetAsync(counts, 0, N * sizeof(int), s_side);
    hist_kernel<<<(E4 + B - 1) / B, B, 0, s_side>>>(dst, E, counts);
    blocksum_kernel<<<NB, 256, 0, s_side>>>(counts, bsums, N);
    scan_bsums_kernel<<<1, 256, 0, s_side>>>(bsums, NB, offsets, N);
    offsets_kernel<<<NB, 256, 0, s_side>>>(counts, bsums, offsets, cursor, dis, N);
    fill_kernel<<<(E4 + B - 1) / B, B, 0, s_side>>>(src, dst, E, cursor, csr);
    cudaEventRecord(ev_join, s_side);

    // GEMM0 does not need dis (scale folded into gather-0's edge loop)
    gemm_scale_kernel<128, 128, false><<<(N + 127) / 128, 256>>>(x, cw0, nullptr, hs, N);

    cudaStreamWaitEvent(0, ev_join, 0);
    // ---- join ----

    // Layer 0: gather with per-edge dis scaling
    gather_combine_kernel<128, true><<<gwarp, B>>>(hs, csr, offsets, cb0, dis, xb, N);
    // Layer 1: 128 -> 64 (dis folded into GEMM epilogue)
    gemm_scale_kernel<128, 64, true><<<(N + 127) / 128, 256>>>(xb, cw1, dis, hs, N);
    gather_combine_kernel<64, false><<<gwarp, B>>>(hs, csr, offsets, cb1, dis, xb, N);
    // Layer 2: 64 -> 32
    gemm_scale_kernel<64, 32, true><<<(N + 127) / 128, 256>>>(xb, cw2, dis, hs, N);
    gather_combine_kernel<32, false><<<gwarp, B>>>(hs, csr, offsets, cb2, dis, xb, N);

    mlp_kernel<<<(N + B - 1) / B, B>>>(xb, lw0, lb0, lw1, lb1, lw2, lb2, sc, N);
    edge_score_kernel<<<(EP + B - 1) / B, B>>>(pe, sc, out, EP);
}

// round 14
// speedup vs baseline: 1.2367x; 1.2367x over previous
#include <cuda_runtime.h>
#include <cuda_fp16.h>
#include <mma.h>
#include <math.h>

using namespace nvcuda;

#define NMAX 50000
#define EMAX 800000
#define DMAX 128

// Scratch (device globals; no allocation in kernel_launch)
__device__ __half g_hs[NMAX * DMAX];   // h (= x@W) payload in fp16
__device__ __half g_xh[NMAX * DMAX];   // layer activations (fp16)
__device__ float g_dis[NMAX];          // rsqrt(deg+1)
__device__ float g_s[NMAX];            // node scores
__device__ int   g_counts[NMAX];       // in-degree histogram
__device__ int   g_offsets[NMAX + 1];  // CSR row offsets
__device__ int   g_cursor[NMAX];       // fill cursors
__device__ int   g_csr[EMAX];          // CSR src indices grouped by dst
__device__ int   g_bsums[256];         // scan block partials

// ---------------------------------------------------------------------------
// Histogram, 4 edges per thread (int4)
__global__ void hist_kernel(const int* __restrict__ dst, int E, int* counts) {
    int i = blockIdx.x * blockDim.x + threadIdx.x;
    int E4 = E >> 2;
    if (i < E4) {
        int4 d = ((const int4*)dst)[i];
        atomicAdd(&counts[d.x], 1);
        atomicAdd(&counts[d.y], 1);
        atomicAdd(&counts[d.z], 1);
        atomicAdd(&counts[d.w], 1);
    }
    int t = E4 * 4 + i;
    if (i < (E & 3)) atomicAdd(&counts[dst[t]], 1);
}

// Two-level exclusive scan
__global__ void blocksum_kernel(const int* __restrict__ counts, int* bsums, int n) {
    __shared__ int sh[256];
    int i = blockIdx.x * 256 + threadIdx.x;
    sh[threadIdx.x] = (i < n) ? counts[i] : 0;
    __syncthreads();
#pragma unroll
    for (int off = 128; off > 0; off >>= 1) {
        if (threadIdx.x < off) sh[threadIdx.x] += sh[threadIdx.x + off];
        __syncthreads();
    }
    if (threadIdx.x == 0) bsums[blockIdx.x] = sh[0];
}

__global__ void scan_bsums_kernel(int* bsums, int nb, int* offsets, int n) {
    __shared__ int sh[256];
    int t = threadIdx.x;
    int v = (t < nb) ? bsums[t] : 0;
    sh[t] = v;
    __syncthreads();
#pragma unroll
    for (int off = 1; off < 256; off <<= 1) {
        int u = (t >= off) ? sh[t - off] : 0;
        __syncthreads();
        sh[t] += u;
        __syncthreads();
    }
    if (t < nb) bsums[t] = sh[t] - v;  // exclusive
    if (t == 255) offsets[n] = sh[255];
}

__global__ void offsets_kernel(const int* __restrict__ counts,
                               const int* __restrict__ bsums,
                               int* offsets, int* cursor, float* dis, int n) {
    __shared__ int sh[256];
    int t = threadIdx.x;
    int i = blockIdx.x * 256 + t;
    int v = (i < n) ? counts[i] : 0;
    sh[t] = v;
    __syncthreads();
#pragma unroll
    for (int off = 1; off < 256; off <<= 1) {
        int u = (t >= off) ? sh[t - off] : 0;
        __syncthreads();
        sh[t] += u;
        __syncthreads();
    }
    if (i < n) {
        int o = bsums[blockIdx.x] + sh[t] - v;
        offsets[i] = o;
        cursor[i] = o;
        dis[i] = rsqrtf((float)v + 1.0f);
    }
}

// CSR fill, 4 edges per thread
__global__ void fill_kernel(const int* __restrict__ src,
                            const int* __restrict__ dst, int E,
                            int* cursor, int* __restrict__ csr) {
    int i = blockIdx.x * blockDim.x + threadIdx.x;
    int E4 = E >> 2;
    if (i < E4) {
        int4 s = ((const int4*)src)[i];
        int4 d = ((const int4*)dst)[i];
        int p0 = atomicAdd(&cursor[d.x], 1);
        int p1 = atomicAdd(&cursor[d.y], 1);
        int p2 = atomicAdd(&cursor[d.z], 1);
        int p3 = atomicAdd(&cursor[d.w], 1);
        csr[p0] = s.x;
        csr[p1] = s.y;
        csr[p2] = s.z;
        csr[p3] = s.w;
    }
    int t = E4 * 4 + i;
    if (i < (E & 3)) {
        int pos = atomicAdd(&cursor[dst[t]], 1);
        csr[pos] = src[t];
    }
}

// ---------------------------------------------------------------------------
// Tensor-core GEMM (wmma / HMMA, fp16 in, fp32 accumulate) + row scale.
// out[r, c] = half((A@W)[r, c] * (SCALE ? dis[r] : 1)).
// BM=64 rows/block, 256 threads (8 warps). A is AT (float or __half);
// W is fp32 and converted to fp16 in the smem stage.
template <int DIN, int DOUT, bool SCALE, typename AT>
__global__ void __launch_bounds__(256)
wmma_gemm_kernel(const AT* __restrict__ A, const float* __restrict__ W,
                 const float* __restrict__ dis, __half* __restrict__ out, int n) {
    constexpr int BM = 64;
    constexpr int WARPS_N = (DOUT == 128) ? 4 : 2;
    constexpr int WARPS_M = 8 / WARPS_N;        // 2 or 4
    constexpr int WM = BM / WARPS_M;            // 32 or 16
    constexpr int WN = DOUT / WARPS_N;          // 32 / 32 / 16
    constexpr int MF = WM / 16;                 // 2 or 1
    constexpr int NF = WN / 16;                 // 2 or 1

    __shared__ __half As[BM * 16];              // 2 KB
    __shared__ __half Ws[16 * DOUT];            // <= 4 KB
    __shared__ float  Cs[BM * DOUT];            // <= 32 KB

    int tid = threadIdx.x;
    int wid = tid >> 5;
    int wm = wid / WARPS_N, wn = wid % WARPS_N;
    int row0 = blockIdx.x * BM;

    wmma::fragment<wmma::accumulator, 16, 16, 16, float> cf[MF][NF];
#pragma unroll
    for (int mf = 0; mf < MF; mf++)
#pragma unroll
        for (int nf = 0; nf < NF; nf++) wmma::fill_fragment(cf[mf][nf], 0.0f);

    for (int k0 = 0; k0 < DIN; k0 += 16) {
        // A stage: 64 rows x 16 k, 4 elements per thread, convert to fp16
        {
            int r = tid >> 2;           // 0..63
            int c = (tid & 3) * 4;      // 0,4,8,12
            int gr = row0 + r;
            __half h[4];
            if (gr < n) {
                if constexpr (sizeof(AT) == 4) {
                    float4 v = *(const float4*)&A[(size_t)gr * DIN + k0 + c];
                    h[0] = __float2half_rn(v.x);
                    h[1] = __float2half_rn(v.y);
                    h[2] = __float2half_rn(v.z);
                    h[3] = __float2half_rn(v.w);
                } else {
                    uint2 v = *(const uint2*)&A[(size_t)gr * DIN + k0 + c];
                    *(uint2*)h = v;
                }
            } else {
                h[0] = h[1] = h[2] = h[3] = __ushort_as_half(0);
            }
            *(uint2*)&As[r * 16 + c] = *(uint2*)h;
        }
        // W stage: 16 x DOUT fp32 -> fp16
        for (int i = tid * 4; i < 16 * DOUT; i += 256 * 4) {
            int kr = i / DOUT, c = i % DOUT;
            float4 v = *(const float4*)&W[(size_t)(k0 + kr) * DOUT + c];
            __half h[4] = {__float2half_rn(v.x), __float2half_rn(v.y),
                           __float2half_rn(v.z), __float2half_rn(v.w)};
            *(uint2*)&Ws[i] = *(uint2*)h;
        }
        __syncthreads();

        wmma::fragment<wmma::matrix_a, 16, 16, 16, __half, wmma::row_major> af[MF];
        wmma::fragment<wmma::matrix_b, 16, 16, 16, __half, wmma::row_major> bf[NF];
#pragma unroll
        for (int mf = 0; mf < MF; mf++)
            wmma::load_matrix_sync(af[mf], &As[(wm * WM + mf * 16) * 16], 16);
#pragma unroll
        for (int nf = 0; nf < NF; nf++)
            wmma::load_matrix_sync(bf[nf], &Ws[wn * WN + nf * 16], DOUT);
#pragma unroll
        for (int mf = 0; mf < MF; mf++)
#pragma unroll
            for (int nf = 0; nf < NF; nf++)
                wmma::mma_sync(cf[mf][nf], af[mf], bf[nf], cf[mf][nf]);
        __syncthreads();
    }

    // Epilogue: accum -> smem fp32, then scale + convert + coalesced store
#pragma unroll
    for (int mf = 0; mf < MF; mf++)
#pragma unroll
        for (int nf = 0; nf < NF; nf++)
            wmma::store_matrix_sync(
                &Cs[(wm * WM + mf * 16) * DOUT + wn * WN + nf * 16],
                cf[mf][nf], DOUT, wmma::mem_row_major);
    __syncthreads();

    for (int i = tid * 4; i < BM * DOUT; i += 256 * 4) {
        int r = i / DOUT, c = i % DOUT;
        int gr = row0 + r;
        if (gr < n) {
            float dv = SCALE ? dis[gr] : 1.0f;
            float4 v = *(const float4*)&Cs[i];
            __half2 h0 = __float22half2_rn(make_float2(v.x * dv, v.y * dv));
            __half2 h1 = __float22half2_rn(make_float2(v.z * dv, v.w * dv));
            uint2 pk = make_uint2(*(unsigned*)&h0, *(unsigned*)&h1);
            *(uint2*)&out[(size_t)gr * DOUT + c] = pk;
        }
    }
}

// ---------------------------------------------------------------------------
// fp16 vector loads, fp32 accumulate.
template <int VW>
__device__ __forceinline__ void vload_add_h(const __half* __restrict__ p, float* a) {
    if constexpr (VW == 4) {
        uint2 u = *(const uint2*)p;
        float2 f0 = __half22float2(*(const __half2*)&u.x);
        float2 f1 = __half22float2(*(const __half2*)&u.y);
        a[0] += f0.x; a[1] += f0.y; a[2] += f1.x; a[3] += f1.y;
    } else if constexpr (VW == 2) {
        __half2 h = *(const __half2*)p;
        float2 f = __half22float2(h);
        a[0] += f.x; a[1] += f.y;
    } else {
        a[0] += __half2float(*p);
    }
}
template <int VW>
__device__ __forceinline__ void vload_fma_h(const __half* __restrict__ p, float s,
                                            float* a) {
    if constexpr (VW == 4) {
        uint2 u = *(const uint2*)p;
        float2 f0 = __half22float2(*(const __half2*)&u.x);
        float2 f1 = __half22float2(*(const __half2*)&u.y);
        a[0] += f0.x * s; a[1] += f0.y * s; a[2] += f1.x * s; a[3] += f1.y * s;
    } else if constexpr (VW == 2) {
        __half2 h = *(const __half2*)p;
        float2 f = __half22float2(h);
        a[0] += f.x * s; a[1] += f.y * s;
    } else {
        a[0] += __half2float(*p) * s;
    }
}
template <int VW>
__device__ __forceinline__ void vstore_h(__half* __restrict__ p, const float* r) {
    if constexpr (VW == 4) {
        __half2 h0 = __float22half2_rn(make_float2(r[0], r[1]));
        __half2 h1 = __float22half2_rn(make_float2(r[2], r[3]));
        uint2 pk = make_uint2(*(unsigned*)&h0, *(unsigned*)&h1);
        *(uint2*)p = pk;
    } else if constexpr (VW == 2) {
        *(__half2*)p = __float22half2_rn(make_float2(r[0], r[1]));
    } else {
        *p = __float2half_rn(r[0]);
    }
}

// One warp per node, edge loop unrolled x8, 4 independent accumulators.
// EDGE_SCALE=false: hs = h*dis[row]; out = relu(dis[v]*(acc+hs[v]) + b)
// EDGE_SCALE=true:  hs = h; acc = sum h[src]*dis[src];
//   out = relu(dis[v]*(acc + h[v]*dis[v]) + b).  Output fp16.
template <int DOUT, bool EDGE_SCALE>
__global__ void __launch_bounds__(256)
gather_combine_kernel(const __half* __restrict__ hs,
                      const int* __restrict__ csr,
                      const int* __restrict__ offsets,
                      const float* __restrict__ b,
                      const float* __restrict__ dis,
                      __half* __restrict__ out, int n) {
    constexpr int VW = DOUT / 32;
    int warp = (blockIdx.x * blockDim.x + threadIdx.x) >> 5;
    int lane = threadIdx.x & 31;
    if (warp >= n) return;
    int v = warp;
    int s0 = offsets[v], s1 = offsets[v + 1];

    float a0[VW] = {}, a1[VW] = {}, a2[VW] = {}, a3[VW] = {};
    int fo = lane * VW;
    const __half* __restrict__ base = hs + fo;

    int e = s0;
    for (; e + 8 <= s1; e += 8) {
        int i0 = __ldg(&csr[e]);
        int i1 = __ldg(&csr[e + 1]);
        int i2 = __ldg(&csr[e + 2]);
        int i3 = __ldg(&csr[e + 3]);
        int i4 = __ldg(&csr[e + 4]);
        int i5 = __ldg(&csr[e + 5]);
        int i6 = __ldg(&csr[e + 6]);
        int i7 = __ldg(&csr[e + 7]);
        if constexpr (EDGE_SCALE) {
            float d0 = __ldg(&dis[i0]);
            float d1 = __ldg(&dis[i1]);
            float d2 = __ldg(&dis[i2]);
            float d3 = __ldg(&dis[i3]);
            float d4 = __ldg(&dis[i4]);
            float d5 = __ldg(&dis[i5]);
            float d6 = __ldg(&dis[i6]);
            float d7 = __ldg(&dis[i7]);
            vload_fma_h<VW>(base + (size_t)i0 * DOUT, d0, a0);
            vload_fma_h<VW>(base + (size_t)i1 * DOUT, d1, a1);
            vload_fma_h<VW>(base + (size_t)i2 * DOUT, d2, a2);
            vload_fma_h<VW>(base + (size_t)i3 * DOUT, d3, a3);
            vload_fma_h<VW>(base + (size_t)i4 * DOUT, d4, a0);
            vload_fma_h<VW>(base + (size_t)i5 * DOUT, d5, a1);
            vload_fma_h<VW>(base + (size_t)i6 * DOUT, d6, a2);
            vload_fma_h<VW>(base + (size_t)i7 * DOUT, d7, a3);
        } else {
            vload_add_h<VW>(base + (size_t)i0 * DOUT, a0);
            vload_add_h<VW>(base + (size_t)i1 * DOUT, a1);
            vload_add_h<VW>(base + (size_t)i2 * DOUT, a2);
            vload_add_h<VW>(base + (size_t)i3 * DOUT, a3);
            vload_add_h<VW>(base + (size_t)i4 * DOUT, a0);
            vload_add_h<VW>(base + (size_t)i5 * DOUT, a1);
            vload_add_h<VW>(base + (size_t)i6 * DOUT, a2);
            vload_add_h<VW>(base + (size_t)i7 * DOUT, a3);
        }
    }
    for (; e + 2 <= s1; e += 2) {
        int i0 = __ldg(&csr[e]);
        int i1 = __ldg(&csr[e + 1]);
        if constexpr (EDGE_SCALE) {
            float d0 = __ldg(&dis[i0]);
            float d1 = __ldg(&dis[i1]);
            vload_fma_h<VW>(base + (size_t)i0 * DOUT, d0, a0);
            vload_fma_h<VW>(base + (size_t)i1 * DOUT, d1, a1);
        } else {
            vload_add_h<VW>(base + (size_t)i0 * DOUT, a0);
            vload_add_h<VW>(base + (size_t)i1 * DOUT, a1);
        }
    }
    if (e < s1) {
        int i0 = __ldg(&csr[e]);
        if constexpr (EDGE_SCALE) {
            float d0 = __ldg(&dis[i0]);
            vload_fma_h<VW>(base + (size_t)i0 * DOUT, d0, a2);
        } else {
            vload_add_h<VW>(base + (size_t)i0 * DOUT, a2);
        }
    }

    float dv = dis[v];
    const __half* hp = hs + (size_t)v * DOUT + fo;
    __half* op = out + (size_t)v * DOUT + fo;

    // Self term: hs[v] (already row-scaled when !EDGE_SCALE) or h[v]*dis[v].
    float self[VW] = {};
    if constexpr (EDGE_SCALE) {
        vload_fma_h<VW>(hp, dv, self);
    } else {
        vload_add_h<VW>(hp, self);
    }

    float r[VW];
#pragma unroll
    for (int j = 0; j < VW; j++) {
        float t = dv * ((a0[j] + a1[j]) + (a2[j] + a3[j]) + self[j]) + b[fo + j];
        r[j] = t > 0.0f ? t : 0.0f;
    }
    vstore_h<VW>(op, r);
}

// ---------------------------------------------------------------------------
__global__ void mlp_kernel(const __half* __restrict__ x,
                           const float* __restrict__ lw0, const float* __restrict__ lb0,
                           const float* __restrict__ lw1, const float* __restrict__ lb1,
                           const float* __restrict__ lw2, const float* __restrict__ lb2,
                           float* __restrict__ s, int n) {
    __shared__ float w0[32 * 16], b0[16], w1[16 * 8], b1[8], w2[8], b2s[1];
    int t = threadIdx.x;
    for (int j = t; j < 32 * 16; j += blockDim.x) w0[j] = lw0[j];
    for (int j = t; j < 16; j += blockDim.x) b0[j] = lb0[j];
    for (int j = t; j < 16 * 8; j += blockDim.x) w1[j] = lw1[j];
    for (int j = t; j < 8; j += blockDim.x) b1[j] = lb1[j];
    for (int j = t; j < 8; j += blockDim.x) w2[j] = lw2[j];
    if (t == 0) b2s[0] = lb2[0];
    __syncthreads();

    int i = blockIdx.x * blockDim.x + t;
    if (i >= n) return;

    float xv[32];
    const __half2* xp = (const __half2*)(x + (size_t)i * 32);
#pragma unroll
    for (int k = 0; k < 16; k++) {
        float2 f = __half22float2(xp[k]);
        xv[2 * k] = f.x;
        xv[2 * k + 1] = f.y;
    }

    float y1[16];
#pragma unroll
    for (int j = 0; j < 16; j++) {
        float a = b0[j];
#pragma unroll
        for (int k = 0; k < 32; k++) a += xv[k] * w0[k * 16 + j];
        y1[j] = a > 0.0f ? a : 0.0f;
    }
    float y2[8];
#pragma unroll
    for (int j = 0; j < 8; j++) {
        float a = b1[j];
#pragma unroll
        for (int k = 0; k < 16; k++) a += y1[k] * w1[k * 8 + j];
        y2[j] = a > 0.0f ? a : 0.0f;
    }
    float z = b2s[0];
#pragma unroll
    for (int k = 0; k < 8; k++) z += y2[k] * w2[k];
    s[i] = 1.0f / (1.0f + expf(-z));
}

__global__ void edge_score_kernel(const int* __restrict__ pe,
                                  const float* __restrict__ s,
                                  float* __restrict__ out, int ep) {
    int i = blockIdx.x * blockDim.x + threadIdx.x;
    if (i < ep) {
        int2 p = ((const int2*)pe)[i];
        out[i] = s[p.x] * s[p.y];
    }
}

// ---------------------------------------------------------------------------
extern "C" void kernel_launch(void* const* d_in, const int* in_sizes, int n_in,
                              void* d_out, int out_size) {
    const float* x   = (const float*)d_in[0];
    const int* ei    = (const int*)d_in[1];
    const int* pe    = (const int*)d_in[2];
    const float* cw0 = (const float*)d_in[3];
    const float* cb0 = (const float*)d_in[4];
    const float* cw1 = (const float*)d_in[5];
    const float* cb1 = (const float*)d_in[6];
    const float* cw2 = (const float*)d_in[7];
    const float* cb2 = (const float*)d_in[8];
    const float* lw0 = (const float*)d_in[9];
    const float* lb0 = (const float*)d_in[10];
    const float* lw1 = (const float*)d_in[11];
    const float* lb1 = (const float*)d_in[12];
    const float* lw2 = (const float*)d_in[13];
    const float* lb2 = (const float*)d_in[14];
    float* out = (float*)d_out;

    const int N  = in_sizes[0] / 128;
    const int E  = in_sizes[1] / 2;
    const int EP = out_size;

    const int* src = ei;
    const int* dst = ei + E;

    float *dis, *sc;
    __half *hs, *xb;
    int *counts, *offsets, *cursor, *csr, *bsums;
    cudaGetSymbolAddress((void**)&hs, g_hs);
    cudaGetSymbolAddress((void**)&xb, g_xh);
    cudaGetSymbolAddress((void**)&dis, g_dis);
    cudaGetSymbolAddress((void**)&sc, g_s);
    cudaGetSymbolAddress((void**)&counts, g_counts);
    cudaGetSymbolAddress((void**)&offsets, g_offsets);
    cudaGetSymbolAddress((void**)&cursor, g_cursor);
    cudaGetSymbolAddress((void**)&csr, g_csr);
    cudaGetSymbolAddress((void**)&bsums, g_bsums);

    // Lazy side-stream + events for capture-legal fork/join.
    static cudaStream_t s_side = nullptr;
    static cudaEvent_t ev_fork = nullptr, ev_join = nullptr;
    if (!s_side) {
        cudaStreamCreateWithFlags(&s_side, cudaStreamNonBlocking);
        cudaEventCreateWithFlags(&ev_fork, cudaEventDisableTiming);
        cudaEventCreateWithFlags(&ev_join, cudaEventDisableTiming);
    }

    const int B = 256;
    const int NB = (N + 255) / 256;
    const int E4 = (E + 3) / 4;
    int gwarp = (N * 32 + B - 1) / B;   // 1 warp per node
    int gemmb = (N + 63) / 64;          // BM=64 rows per block

    // ---- fork: CSR build + dis on side stream, GEMM0 on main ----
    cudaEventRecord(ev_fork, 0);
    cudaStreamWaitEvent(s_side, ev_fork, 0);

    cudaMemsetAsync(counts, 0, N * sizeof(int), s_side);
    hist_kernel<<<(E4 + B - 1) / B, B, 0, s_side>>>(dst, E, counts);
    blocksum_kernel<<<NB, 256, 0, s_side>>>(counts, bsums, N);
    scan_bsums_kernel<<<1, 256, 0, s_side>>>(bsums, NB, offsets, N);
    offsets_kernel<<<NB, 256, 0, s_side>>>(counts, bsums, offsets, cursor, dis, N);
    fill_kernel<<<(E4 + B - 1) / B, B, 0, s_side>>>(src, dst, E, cursor, csr);
    cudaEventRecord(ev_join, s_side);

    // GEMM0 does not need dis (scale folded into gather-0's edge loop)
    wmma_gemm_kernel<128, 128, false, float><<<gemmb, 256>>>(x, cw0, nullptr, hs, N);

    cudaStreamWaitEvent(0, ev_join, 0);
    // ---- join ----

    // Layer 0: gather with per-edge dis scaling
    gather_combine_kernel<128, true><<<gwarp, B>>>(hs, csr, offsets, cb0, dis, xb, N);
    // Layer 1: 128 -> 64 (dis folded into GEMM epilogue)
    wmma_gemm_kernel<128, 64, true, __half><<<gemmb, 256>>>(xb, cw1, dis, hs, N);
    gather_combine_kernel<64, false><<<gwarp, B>>>(hs, csr, offsets, cb1, dis, xb, N);
    // Layer 2: 64 -> 32
    wmma_gemm_kernel<64, 32, true, __half><<<gemmb, 256>>>(xb, cw2, dis, hs, N);
    gather_combine_kernel<32, false><<<gwarp, B>>>(hs, csr, offsets, cb2, dis, xb, N);

    mlp_kernel<<<(N + B - 1) / B, B>>>(xb, lw0, lb0, lw1, lb1, lw2, lb2, sc, N);
    edge_score_kernel<<<(EP + B - 1) / B, B>>>(pe, sc, out, EP);
}